// round 17
// baseline (speedup 1.0000x reference)
#include <cuda_runtime.h>
#include <cuda_fp16.h>
#include <math.h>
#include <cstdint>

// ---------------------------------------------------------------------------
// Problem constants
// ---------------------------------------------------------------------------
#define BATCH 4
#define SEQ   1024
#define D     768
#define DH    769
#define HEADS 12
#define HDIM  64
#define BH    (BATCH*HEADS)      // 48
#define ROWS  (BATCH*SEQ)        // 4096
#define DM    3072
#define DMH   3073
#define KP1   832                // DH padded to mult of 64
#define KP2   3136               // DMH padded to mult of 64

// ---------------------------------------------------------------------------
// Scratch
// ---------------------------------------------------------------------------
__device__ float g_QKVf[3*BH*SEQ*HDIM];
__device__ float g_qt [BH*SEQ];
__device__ float g_kt [BH*SEQ];
__device__ float g_Th [ROWS*HEADS];
__device__ float g_MO [ROWS*D];
__device__ float g_OUT[ROWS*D];
__device__ float g_G2 [ROWS*D];

// fp16 per-head planes for attention
__device__ __half g_Qsp[BH*SEQ*HDIM];
__device__ __half g_Ksp[BH*SEQ*HDIM];
__device__ __half g_Vsp[BH*SEQ*HDIM];

// fp16 single-plane activations (GEMM A operands)
__device__ __half g_X1f [ROWS*KP1];
__device__ __half g_AINf[ROWS*KP1];
__device__ __half g_Hf  [ROWS*KP1];
__device__ __half g_H1f [ROWS*KP2];

// fp16 single-plane weights (GEMM B operands)
__device__ __half g_Wqkv[3*D*KP1];
__device__ __half g_Wo [D*KP1];
__device__ __half g_W1 [DM*KP1];
__device__ __half g_W2 [D*KP2];

// ---------------------------------------------------------------------------
// Helpers
// ---------------------------------------------------------------------------
__device__ __forceinline__ float warpSum(float v){
  #pragma unroll
  for(int o=16;o>0;o>>=1) v += __shfl_xor_sync(0xffffffffu, v, o);
  return v;
}
__device__ __forceinline__ float blockSum(float v, float* sh){
  int lane = threadIdx.x & 31, w = threadIdx.x >> 5;
  v = warpSum(v);
  if(lane==0) sh[w] = v;
  __syncthreads();
  float r = (threadIdx.x < 8) ? sh[threadIdx.x] : 0.f;
  if(w==0) r = warpSum(r);
  if(threadIdx.x==0) sh[0] = r;
  __syncthreads();
  r = sh[0];
  __syncthreads();
  return r;
}
__device__ __forceinline__ void packhiHf(float a, float b, unsigned &h){
  __half2 hp; hp.x = __float2half(a); hp.y = __float2half(b);
  h = *(unsigned*)&hp;
}
__device__ __forceinline__ void cpasync16(void* s, const void* g){
  unsigned int sa = (unsigned int)__cvta_generic_to_shared(s);
  asm volatile("cp.async.cg.shared.global [%0], [%1], 16;\n" :: "r"(sa), "l"(g));
}
#define CP_COMMIT asm volatile("cp.async.commit_group;\n")
#define CP_WAIT(n) asm volatile("cp.async.wait_group %0;\n" :: "n"(n))

__device__ __forceinline__ void mma16816hf(float* d, const unsigned* a, const unsigned* b){
  asm volatile("mma.sync.aligned.m16n8k16.row.col.f32.f16.f16.f32 "
    "{%0,%1,%2,%3},{%4,%5,%6,%7},{%8,%9},{%0,%1,%2,%3};"
    : "+f"(d[0]),"+f"(d[1]),"+f"(d[2]),"+f"(d[3])
    : "r"(a[0]),"r"(a[1]),"r"(a[2]),"r"(a[3]),"r"(b[0]),"r"(b[1]));
}
__device__ __forceinline__ void ldsm4(unsigned* r, unsigned addr){
  asm volatile("ldmatrix.sync.aligned.m8n8.x4.shared.b16 {%0,%1,%2,%3}, [%4];"
    : "=r"(r[0]),"=r"(r[1]),"=r"(r[2]),"=r"(r[3]) : "r"(addr));
}
__device__ __forceinline__ void ldsm4t(unsigned* r, unsigned addr){
  asm volatile("ldmatrix.sync.aligned.m8n8.x4.trans.shared.b16 {%0,%1,%2,%3}, [%4];"
    : "=r"(r[0]),"=r"(r[1]),"=r"(r[2]),"=r"(r[3]) : "r"(addr));
}

// ---------------------------------------------------------------------------
// Weight converts (single fp16 plane)
// ---------------------------------------------------------------------------
__global__ void conv_kernel(const float* __restrict__ W,
                            __half* __restrict__ Wh,
                            int Kk, int KPp, int total)
{
  int i = blockIdx.x*256 + threadIdx.x;
  if(i >= total) return;
  int r = i / Kk, c = i - r*Kk;
  Wh[(size_t)r*KPp + c] = __float2half(W[i]);
}

// converts Wq|Wk|Wv into g_Wqkv and Wo into g_Wo in one launch
__global__ void conv_qkvo_kernel(const float* __restrict__ Wq,
                                 const float* __restrict__ Wk,
                                 const float* __restrict__ Wv,
                                 const float* __restrict__ Wo,
                                 __half* __restrict__ Wqkv,
                                 __half* __restrict__ Woh)
{
  int i = blockIdx.x*256 + threadIdx.x;
  if(i >= 4*D*DH) return;
  int r = i / DH, c = i - r*DH;
  int sel = r / D, rl = r - sel*D;
  const float* src = (sel==0)? Wq : (sel==1)? Wk : (sel==2)? Wv : Wo;
  __half v = __float2half(src[(size_t)rl*DH + c]);
  if(sel < 3) Wqkv[(size_t)r*KP1 + c] = v;
  else        Woh [(size_t)rl*KP1 + c] = v;
}

// ---------------------------------------------------------------------------
// LayerNorm (+optional add) + add_time -> single fp16 plane
// ---------------------------------------------------------------------------
__global__ void ln_addtime_kernel(const float* __restrict__ in1, int ld1, int off1,
                                  const float* __restrict__ in2, int ld2, int off2,
                                  const float* __restrict__ gv, const float* __restrict__ bv,
                                  __half* __restrict__ outp,
                                  float* __restrict__ rawOut)
{
  __shared__ float red[8];
  int row = blockIdx.x, tid = threadIdx.x;
  float v[3];
  #pragma unroll
  for(int q=0;q<3;q++){
    int j = tid + q*256;
    float x = in1[(size_t)row*ld1 + off1 + j];
    if(in2) x += in2[(size_t)row*ld2 + off2 + j];
    v[q] = x;
    if(rawOut) rawOut[(size_t)row*D + j] = x;
  }
  float s  = v[0]+v[1]+v[2];
  float s2 = v[0]*v[0]+v[1]*v[1]+v[2]*v[2];
  s  = blockSum(s,  red);
  float mu = s * (1.f/768.f);
  s2 = blockSum(s2, red);
  float var = s2*(1.f/768.f) - mu*mu;
  float rstd = rsqrtf(var + 1e-5f);
  float w[3]; float n2 = 0.f;
  #pragma unroll
  for(int q=0;q<3;q++){
    int j = tid + q*256;
    w[q] = (v[q]-mu)*rstd*gv[j] + bv[j];
    n2 += w[q]*w[q];
  }
  n2 = blockSum(n2, red);
  #pragma unroll
  for(int q=0;q<3;q++){
    int j = tid + q*256;
    outp[(size_t)row*KP1 + 1 + j] = __float2half(w[q]);
  }
  if(tid==0) outp[(size_t)row*KP1] = __float2half(sqrtf(1.f + n2));
}

// ---------------------------------------------------------------------------
// Pure fp16 GEMM, BK=64: C[M,N] = A[M,K]*B[N,K]^T
//   128x128 CTA tile, 16 warps (4x4), 32x32 warp tile, 512 threads,
//   3-stage cp.async pipeline, 32 MMA + 16 ldsm per iter, 1 sync per 64-K.
//   mode 0: fp32 out; 1: fused-QKV head-scatter; 2: gelu + fp16 out.
// ---------------------------------------------------------------------------
#define HGB_STR    72                    // halves per smem row
#define HG_PLANE_H (128*HGB_STR)         // 9216 halves
#define HG_STAGE_H (2*HG_PLANE_H)        // 18432 halves
#define HG_STAGE_BYTES (HG_STAGE_H*2)    // 36864
#define HG_SMEM_BYTES (3*HG_STAGE_BYTES) // 110592

__global__ void __launch_bounds__(512,1) hgemm_kernel(
    const __half* __restrict__ Ah,
    const __half* __restrict__ Bh,
    float* __restrict__ Cf, __half* __restrict__ Ch,
    int KP, int ldc, int mode)
{
  extern __shared__ __half smb[];
  int tid = threadIdx.x;
  int lane = tid & 31, wid = tid >> 5;
  int wm = wid >> 2, wn = wid & 3;
  int g = lane >> 2, t = lane & 3;
  int row0 = blockIdx.y*128, col0 = blockIdx.x*128;

  float acc[2][4][4];
  #pragma unroll
  for(int mi=0;mi<2;mi++)
    #pragma unroll
    for(int ni=0;ni<4;ni++)
      #pragma unroll
      for(int e=0;e<4;e++) acc[mi][ni][e]=0.f;

  const int niter = KP >> 6;
  const unsigned smemU = (unsigned)__cvta_generic_to_shared(smb);

  // A ldmatrix (per mi, per ks): 16 rows x 16 cols
  const int aRow = wm*32 + (lane&7) + ((lane>>3)&1)*8;
  const int aCol = ((lane>>4)&1)*8;
  const unsigned aOffB = (unsigned)((aRow*HGB_STR + aCol)*2);
  // B ldmatrix x4: 8 n-rows x 4 consecutive k-octets (covers k32 per ldsm)
  const unsigned bOffB = (unsigned)(HG_PLANE_H*2 + (lane&7)*(HGB_STR*2) + (lane>>3)*16);

  // stage loader: 2 planes x 128 rows x 8 chunks = 2048 chunks, 4/thread
  #define LOAD_STAGE(stg, k0) do{                                             \
    __half* s = smb + (stg)*HG_STAGE_H;                                       \
    _Pragma("unroll")                                                         \
    for(int q_=0;q_<4;q_++){                                                  \
      int idx_ = tid + q_*512;                                                \
      int p_ = idx_ >> 10, w_ = idx_ & 1023;                                  \
      int r_ = w_ >> 3, cc_ = (w_ & 7)*8;                                     \
      const __half* src_ = (p_==0? Ah : Bh);                                  \
      int grow_ = (p_==0? row0 : col0) + r_;                                  \
      cpasync16(s + p_*HG_PLANE_H + r_*HGB_STR + cc_,                         \
                src_ + (size_t)grow_*KP + (k0) + cc_);                        \
    }                                                                         \
    CP_COMMIT;                                                                \
  } while(0)

  LOAD_STAGE(0, 0);
  LOAD_STAGE(1, 64);

  for(int it=0; it<niter; it++){
    if(it == niter-1){ CP_WAIT(0); } else { CP_WAIT(1); }
    __syncthreads();
    if(it+2 < niter) LOAD_STAGE((it+2)%3, (it+2)<<6);

    const unsigned sb = smemU + (unsigned)((it%3)*HG_STAGE_BYTES);

    // load all B frags for this 64-K chunk: per ni 2 ldsm4 (k0-31, k32-63)
    unsigned b[4][2][4];
    #pragma unroll
    for(int ni=0;ni<4;ni++){
      unsigned bd = sb + bOffB + (unsigned)(wn*32*(HGB_STR*2) + ni*8*(HGB_STR*2));
      ldsm4(b[ni][0], bd);
      ldsm4(b[ni][1], bd + 64);
    }
    #pragma unroll
    for(int ks=0;ks<4;ks++){
      unsigned a_h[2][4];
      #pragma unroll
      for(int mi=0;mi<2;mi++){
        unsigned ad = sb + aOffB + (unsigned)(mi*16*(HGB_STR*2) + ks*32);
        ldsm4(a_h[mi], ad);
      }
      #pragma unroll
      for(int mi=0;mi<2;mi++)
        #pragma unroll
        for(int ni=0;ni<4;ni++)
          mma16816hf(acc[mi][ni], a_h[mi], b[ni][ks>>1] + (ks&1)*2);
    }
  }

  // ---- epilogue ----
  int mat = blockIdx.x / 6;
  int cmatBase = mat*768;
  #pragma unroll
  for(int mi=0;mi<2;mi++){
    int rb = row0 + wm*32 + mi*16 + g;
    #pragma unroll
    for(int ni=0;ni<4;ni++){
      int cb = col0 + wn*32 + ni*8 + 2*t;
      float* a = acc[mi][ni];
      #pragma unroll
      for(int e=0;e<4;e++){
        int r = rb + (e>=2 ? 8 : 0);
        int c = cb + (e&1);
        float v = a[e];
        if(mode==2){
          v = 0.5f*v*(1.f + erff(v*0.70710678118654752f));
          Ch[(size_t)r*ldc + c] = __float2half(v);
        } else if(mode==1){
          int b_ = r >> 10, ii = r & 1023;
          int cmat = c - cmatBase;
          int h = cmat >> 6, cc2 = cmat & 63;
          Cf[(size_t)mat*(BH*SEQ*HDIM) + (size_t)(((b_*HEADS+h)<<10) + ii)*HDIM + cc2] = v;
        } else {
          Cf[(size_t)r*ldc + c] = v;
        }
      }
    }
  }
}

// ---------------------------------------------------------------------------
// Prep: qt, kt, v->v_tan; Q,K,V single fp16 planes.
// ---------------------------------------------------------------------------
__global__ void prep_kernel()
{
  int w = blockIdx.x*8 + (threadIdx.x>>5);
  int lane = threadIdx.x & 31;

  const float* q = g_QKVf + (size_t)w*HDIM;
  float qv[2]; float s = 0.f;
  #pragma unroll
  for(int e=0;e<2;e++){ qv[e] = q[lane+32*e]; s += qv[e]*qv[e]; }
  s = warpSum(s);
  if(lane==0) g_qt[w] = sqrtf(1.f + s);
  #pragma unroll
  for(int e=0;e<2;e++)
    g_Qsp[(size_t)w*HDIM + lane+32*e] = __float2half(qv[e]);

  const float* k = g_QKVf + (size_t)(BH*SEQ)*HDIM + (size_t)w*HDIM;
  float kv[2]; s = 0.f;
  #pragma unroll
  for(int e=0;e<2;e++){ kv[e] = k[lane+32*e]; s += kv[e]*kv[e]; }
  s = warpSum(s);
  if(lane==0) g_kt[w] = sqrtf(1.f + s);
  #pragma unroll
  for(int e=0;e<2;e++)
    g_Ksp[(size_t)w*HDIM + lane+32*e] = __float2half(kv[e]);

  const float* v = g_QKVf + (size_t)(2*BH*SEQ)*HDIM + (size_t)w*HDIM;
  float vv[2]; s = 0.f;
  #pragma unroll
  for(int e=0;e<2;e++){ vv[e] = v[lane+32*e]; s += vv[e]*vv[e]; }
  s = warpSum(s);
  float sn = sqrtf(s);
  float vt = sqrtf(1.f + s);
  float vc = fmaxf(vt, 1.0000001f);
  float dist = __logf(vc + sqrtf((vc-1.f)*(vc+1.f)));
  float scl = dist / fmaxf(sn, 1e-8f);
  #pragma unroll
  for(int e=0;e<2;e++)
    g_Vsp[(size_t)w*HDIM + lane+32*e] = __float2half(vv[e]*scl);
}

// ---------------------------------------------------------------------------
// fp16 tensor-core fused hyperbolic flash attention (verified R15).
// ---------------------------------------------------------------------------
#define AT_STR   72
#define AT_PLANE (64*AT_STR)
#define AT_STAGE (2*AT_PLANE)
#define AT_SMEM_BYTES (2*AT_STAGE*2 + 2*64*4)

__device__ __forceinline__ float attn_logit(float sv, float qt, float cq, float rsh,
                                            float Bq, float ktj, float lam, float tau,
                                            float spm){
  float rawc = fmaxf(qt*ktj - sv, 1.0f);
  bool selfp = rawc < 1.00001f;
  float c = selfp ? 2.f : rawc;
  float x = (c-1.f)*(c+1.f);
  float rs = rsqrtf(fmaxf(x, 1e-12f));
  float sh = x*rs;
  float dist = __logf(c + sh);
  float ck = fmaxf(ktj, 1.0000001f);
  float Z = (rawc*cq - ck)*rs*rsh;
  Z = selfp ? 1.f : fminf(fmaxf(Z, -1.f), 1.f);
  float pen = -lam*__logf(1.f + dist*dist);
  float ent = __logf(1.f + __expf(Bq + Z - 0.1f)) - spm;
  return pen - tau*ent;
}

__global__ void __launch_bounds__(256,1) attn_kernel(
    const float* __restrict__ alpha_raw,
    const float* __restrict__ tau_raw,
    const float* __restrict__ lambda_raw)
{
  extern __shared__ __half smA[];
  float* ktsBuf = (float*)(smA + 2*AT_STAGE);

  const int bh = blockIdx.y;
  const int qrow0 = blockIdx.x*128;
  const int tid = threadIdx.x;
  const int lane = tid & 31, wid = tid >> 5;
  const int g = lane >> 2, t = lane & 3;
  const unsigned smemU = (unsigned)__cvta_generic_to_shared(smA);

  const float alpha = log1pf(expf(alpha_raw[0]));
  const float tau   = log1pf(expf(tau_raw[0]));
  const float lam   = log1pf(expf(lambda_raw[0]));
  const float spm   = log1pf(expf(-0.1f));

  {
    const __half* gQ = g_Qsp + ((size_t)bh*SEQ + qrow0)*HDIM;
    #pragma unroll
    for(int itn=0; itn<4; itn++){
      int ch = tid + itn*256;
      int r = ch >> 3, c0 = (ch & 7)*8;
      *(uint4*)(smA + r*AT_STR + c0) = *(const uint4*)(gQ + r*HDIM + c0);
    }
  }
  __syncthreads();

  unsigned qh[4][4];
  {
    const unsigned* pQ = (const unsigned*)smA;
    int rbase = wid*16 + g;
    #pragma unroll
    for(int ks=0; ks<4; ks++){
      int base = rbase*(AT_STR/2) + ks*8 + t;
      qh[ks][0]=pQ[base];               qh[ks][1]=pQ[base+8*(AT_STR/2)];
      qh[ks][2]=pQ[base+4];             qh[ks][3]=pQ[base+8*(AT_STR/2)+4];
    }
  }
  __syncthreads();

  const int rowL = qrow0 + wid*16 + g;
  const int rowH = rowL + 8;
  float qtL = g_qt[bh*SEQ + rowL], qtH = g_qt[bh*SEQ + rowH];
  float cqL = fmaxf(qtL, 1.0000001f), cqH = fmaxf(qtH, 1.0000001f);
  float ctL = fminf(__logf(cqL + sqrtf((cqL-1.f)*(cqL+1.f))), 40.f);
  float ctH = fminf(__logf(cqH + sqrtf((cqH-1.f)*(cqH+1.f))), 40.f);
  float rshL = 1.f/sinhf(ctL), rshH = 1.f/sinhf(ctH);
  float BqL = alpha*ctL/(1.f + alpha*ctL);
  float BqH = alpha*ctH/(1.f + alpha*ctH);

  float accO[8][4];
  #pragma unroll
  for(int ni=0;ni<8;ni++)
    #pragma unroll
    for(int e=0;e<4;e++) accO[ni][e]=0.f;
  float lsumL = 0.f, lsumH = 0.f;

  const __half* gK = g_Ksp + (size_t)bh*SEQ*HDIM;
  const __half* gV = g_Vsp + (size_t)bh*SEQ*HDIM;
  const float* gkt = g_kt + bh*SEQ;

  const int kj = (lane&7) + ((lane>>4)&1)*8;
  const int kd = ((lane>>3)&1)*8;
  const int vj = (lane&7) + ((lane>>3)&1)*8;
  const int vc = ((lane>>4)&1)*8;

  #define AT_LOAD(stg, jb) do{                                                  \
    __half* s = smA + (stg)*AT_STAGE;                                           \
    _Pragma("unroll")                                                           \
    for(int q_=0;q_<4;q_++){                                                    \
      int ch = tid + q_*256;                                                    \
      int pl = ch >> 9, cw = ch & 511;                                          \
      int r_ = cw >> 3, c_ = (cw & 7)*8;                                        \
      const __half* src = (pl==0? gK : gV);                                     \
      cpasync16(s + pl*AT_PLANE + r_*AT_STR + c_,                               \
                src + (size_t)((jb)+r_)*HDIM + c_);                             \
    }                                                                           \
    if(tid < 16) cpasync16(ktsBuf + (stg)*64 + tid*4, gkt + (jb) + tid*4);      \
    CP_COMMIT;                                                                  \
  } while(0)

  AT_LOAD(0, 0);

  for(int jt=0; jt<16; jt++){
    if(jt+1 < 16){ AT_LOAD((jt+1)&1, (jt+1)*64); CP_WAIT(1); }
    else         { CP_WAIT(0); }
    __syncthreads();

    const unsigned sbK = smemU + (unsigned)(((jt&1)*AT_STAGE)*2);
    const unsigned sbV = sbK + (unsigned)(AT_PLANE*2);
    const float* kts = ktsBuf + (jt&1)*64;

    float accS[8][4];
    #pragma unroll
    for(int ni=0;ni<8;ni++)
      #pragma unroll
      for(int e=0;e<4;e++) accS[ni][e]=0.f;

    #pragma unroll
    for(int ks=0; ks<4; ks++){
      #pragma unroll
      for(int np=0; np<4; np++){
        unsigned kb[4];
        unsigned ad = sbK + (unsigned)(((np*16 + kj)*AT_STR + ks*16 + kd)*2);
        ldsm4(kb, ad);
        mma16816hf(accS[2*np],   qh[ks], kb);
        mma16816hf(accS[2*np+1], qh[ks], kb+2);
      }
    }

    #pragma unroll
    for(int ni=0; ni<8; ni++){
      float2 ktp = *(const float2*)&kts[ni*8 + 2*t];
      float z0 = attn_logit(accS[ni][0], qtL, cqL, rshL, BqL, ktp.x, lam, tau, spm);
      float z1 = attn_logit(accS[ni][1], qtL, cqL, rshL, BqL, ktp.y, lam, tau, spm);
      float z2 = attn_logit(accS[ni][2], qtH, cqH, rshH, BqH, ktp.x, lam, tau, spm);
      float z3 = attn_logit(accS[ni][3], qtH, cqH, rshH, BqH, ktp.y, lam, tau, spm);
      float p0 = __expf(z0), p1 = __expf(z1), p2 = __expf(z2), p3 = __expf(z3);
      lsumL += p0 + p1;
      lsumH += p2 + p3;
      accS[ni][0]=p0; accS[ni][1]=p1; accS[ni][2]=p2; accS[ni][3]=p3;
    }

    #pragma unroll
    for(int kc=0; kc<4; kc++){
      unsigned aP[4];
      packhiHf(accS[2*kc  ][0], accS[2*kc  ][1], aP[0]);
      packhiHf(accS[2*kc  ][2], accS[2*kc  ][3], aP[1]);
      packhiHf(accS[2*kc+1][0], accS[2*kc+1][1], aP[2]);
      packhiHf(accS[2*kc+1][2], accS[2*kc+1][3], aP[3]);
      #pragma unroll
      for(int nq=0; nq<4; nq++){
        unsigned voff = (unsigned)(((kc*16 + vj)*AT_STR + nq*16 + vc)*2);
        unsigned vb[4];
        ldsm4t(vb, sbV + voff);
        mma16816hf(accO[2*nq],   aP, vb);
        mma16816hf(accO[2*nq+1], aP, vb+2);
      }
    }
    __syncthreads();
  }

  float lL = lsumL, lH = lsumH;
  #pragma unroll
  for(int o=1;o<4;o<<=1){
    lL += __shfl_xor_sync(0xffffffffu, lL, o);
    lH += __shfl_xor_sync(0xffffffffu, lH, o);
  }
  float invL = 1.f/(lL*(1.f + 1e-8f));
  float invH = 1.f/(lH*(1.f + 1e-8f));

  float agL[8][2], agH[8][2];
  float nnL = 0.f, nnH = 0.f;
  #pragma unroll
  for(int ni=0;ni<8;ni++){
    agL[ni][0] = accO[ni][0]*invL; agL[ni][1] = accO[ni][1]*invL;
    agH[ni][0] = accO[ni][2]*invH; agH[ni][1] = accO[ni][3]*invH;
    nnL += agL[ni][0]*agL[ni][0] + agL[ni][1]*agL[ni][1];
    nnH += agH[ni][0]*agH[ni][0] + agH[ni][1]*agH[ni][1];
  }
  #pragma unroll
  for(int o=1;o<4;o<<=1){
    nnL += __shfl_xor_sync(0xffffffffu, nnL, o);
    nnH += __shfl_xor_sync(0xffffffffu, nnH, o);
  }
  nnL = sqrtf(nnL); nnH = sqrtf(nnH);
  float tL = coshf(nnL), tH = coshf(nnH);
  float sclL = sinhf(nnL)/fmaxf(nnL, 1e-8f);
  float sclH = sinhf(nnH)/fmaxf(nnH, 1e-8f);

  const int b_ = bh / HEADS, h = bh % HEADS;
  const int growL = b_*SEQ + rowL, growH = b_*SEQ + rowH;
  #pragma unroll
  for(int ni=0;ni<8;ni++){
    int c0 = ni*8 + 2*t;
    size_t iL = (size_t)growL*KP1 + 1 + h*HDIM + c0;
    size_t iH = (size_t)growH*KP1 + 1 + h*HDIM + c0;
    g_AINf[iL]     = __float2half(agL[ni][0]*sclL);
    g_AINf[iL + 1] = __float2half(agL[ni][1]*sclL);
    g_AINf[iH]     = __float2half(agH[ni][0]*sclH);
    g_AINf[iH + 1] = __float2half(agH[ni][1]*sclH);
  }
  if(t==0){
    g_Th[growL*HEADS + h] = tL;
    g_Th[growH*HEADS + h] = tH;
  }
}

// t_new
__global__ void tnew_kernel()
{
  int r = blockIdx.x*256 + threadIdx.x;
  if(r >= ROWS) return;
  float s = 0.f;
  #pragma unroll
  for(int h=0; h<HEADS; h++){ float t = g_Th[r*HEADS+h]; s += t*t; }
  g_AINf[(size_t)r*KP1] = __float2half(sqrtf(s - (float)(HEADS-1)));
}

// time col for mlp hidden
__global__ void time_mlp_kernel()
{
  __shared__ float red[8];
  int row = blockIdx.x, tid = threadIdx.x;
  float s = 0.f;
  #pragma unroll
  for(int q=0;q<12;q++){
    float x = __half2float(g_H1f[(size_t)row*KP2 + 1 + tid + q*256]);
    s += x*x;
  }
  s = blockSum(s, red);
  if(tid==0) g_H1f[(size_t)row*KP2] = __float2half(sqrtf(1.f + s));
}

// final
__global__ void final_kernel(float* __restrict__ out)
{
  __shared__ float red[8];
  int row = blockIdx.x, tid = threadIdx.x;
  float v[3]; float s = 0.f;
  #pragma unroll
  for(int q=0;q<3;q++){
    int j = tid + q*256;
    float x = g_G2[(size_t)row*D + j] + g_OUT[(size_t)row*D + j];
    v[q] = x; s += x*x;
  }
  s = blockSum(s, red);
  #pragma unroll
  for(int q=0;q<3;q++){
    int j = tid + q*256;
    out[(size_t)row*DH + 1 + j] = v[q];
  }
  if(tid==0) out[(size_t)row*DH] = sqrtf(1.f + s);
}

// ---------------------------------------------------------------------------
// Launch
// ---------------------------------------------------------------------------
extern "C" void kernel_launch(void* const* d_in, const int* in_sizes, int n_in,
                              void* d_out, int out_size)
{
  const float* x    = (const float*)d_in[0];
  const float* Wq   = (const float*)d_in[1];
  const float* Wk   = (const float*)d_in[2];
  const float* Wv   = (const float*)d_in[3];
  const float* Wo   = (const float*)d_in[4];
  const float* ln1g = (const float*)d_in[5];
  const float* ln1b = (const float*)d_in[6];
  const float* ln2g = (const float*)d_in[7];
  const float* ln2b = (const float*)d_in[8];
  const float* Wm1  = (const float*)d_in[9];
  const float* Wm2  = (const float*)d_in[10];
  const float* araw = (const float*)d_in[11];
  const float* traw = (const float*)d_in[12];
  const float* lraw = (const float*)d_in[13];
  float* out = (float*)d_out;

  float *pQKV, *pMO, *pOUT, *pG2;
  cudaGetSymbolAddress((void**)&pQKV, g_QKVf);
  cudaGetSymbolAddress((void**)&pMO,  g_MO);
  cudaGetSymbolAddress((void**)&pOUT, g_OUT);
  cudaGetSymbolAddress((void**)&pG2,  g_G2);

  __half *pX1f,*pAINf,*pHf,*pH1f;
  __half *pWqkv,*pWo,*pW1,*pW2;
  cudaGetSymbolAddress((void**)&pX1f,  g_X1f);
  cudaGetSymbolAddress((void**)&pAINf, g_AINf);
  cudaGetSymbolAddress((void**)&pHf,   g_Hf);
  cudaGetSymbolAddress((void**)&pH1f,  g_H1f);
  cudaGetSymbolAddress((void**)&pWqkv, g_Wqkv);
  cudaGetSymbolAddress((void**)&pWo,   g_Wo);
  cudaGetSymbolAddress((void**)&pW1,   g_W1);
  cudaGetSymbolAddress((void**)&pW2,   g_W2);

  cudaFuncSetAttribute(hgemm_kernel, cudaFuncAttributeMaxDynamicSharedMemorySize,
                       HG_SMEM_BYTES);
  cudaFuncSetAttribute(attn_kernel, cudaFuncAttributeMaxDynamicSharedMemorySize,
                       AT_SMEM_BYTES);

  // 0: weight converts for QKV + Wo (merged)
  {
    int tq = 4*D*DH;
    conv_qkvo_kernel<<<(tq+255)/256,256>>>(Wq, Wk, Wv, Wo, pWqkv, pWo);
  }

  // 1: ln1 + add_time
  ln_addtime_kernel<<<ROWS,256>>>(x, DH, 1, nullptr, 0, 0, ln1g, ln1b, pX1f, nullptr);

  // 2: fused QKV projection
  dim3 gqkv(2304/128, ROWS/128);
  hgemm_kernel<<<gqkv,512,HG_SMEM_BYTES>>>(pX1f, pWqkv, pQKV,nullptr, KP1, 0, 1);

  // 3: prep
  prep_kernel<<<(BH*SEQ)/8, 256>>>();

  // 4: fused attention
  attn_kernel<<<dim3(SEQ/128, BH), 256, AT_SMEM_BYTES>>>(araw, traw, lraw);

  // 5: t_new
  tnew_kernel<<<ROWS/256, 256>>>();

  // 6: Wm1 convert (deferred)
  {
    int t2 = DM*DH;
    conv_kernel<<<(t2+255)/256,256>>>(Wm1, pW1, DH, KP1, t2);
  }

  // 7: Wo projection
  dim3 g768(D/128, ROWS/128);
  hgemm_kernel<<<g768,512,HG_SMEM_BYTES>>>(pAINf, pWo, pMO,nullptr, KP1, D, 0);

  // 8: residual + ln2
  ln_addtime_kernel<<<ROWS,256>>>(pMO, D, 0, x, DH, 1, ln2g, ln2b, pHf, pOUT);

  // 9: MLP up with gelu
  dim3 g3072(DM/128, ROWS/128);
  hgemm_kernel<<<g3072,512,HG_SMEM_BYTES>>>(pHf, pW1, nullptr, pH1f+1, KP1, KP2, 2);

  // 10: Wm2 convert (deferred)
  {
    int t3 = D*DMH;
    conv_kernel<<<(t3+255)/256,256>>>(Wm2, pW2, DMH, KP2, t3);
  }

  // 11: mlp hidden time col
  time_mlp_kernel<<<ROWS,256>>>();

  // 12: MLP down
  hgemm_kernel<<<g768,512,HG_SMEM_BYTES>>>(pH1f, pW2, pG2,nullptr, KP2, D, 0);

  // 13: final
  final_kernel<<<ROWS,256>>>(out);
}